// round 1
// baseline (speedup 1.0000x reference)
#include <cuda_runtime.h>
#include <math.h>

#define NN   50000
#define EE   1600000
#define KDIM 1433
#define HID  64
#define AD   32
#define NC   7

// ---------------- scratch (device globals; no allocs allowed) ----------------
__device__ float g_y[(size_t)NN * HID];   // dis[i] * (x @ W_gcn)  [N,64]
__device__ int   g_deg[NN];
__device__ float g_dis[NN];
__device__ int   g_rowptr[NN + 1];
__device__ int   g_cursor[NN];
__device__ int   g_csr[EE];

// ---------------- degree / CSR build ----------------
__global__ void k_zero_deg() {
    int i = blockIdx.x * blockDim.x + threadIdx.x;
    if (i < NN) g_deg[i] = 0;
}

__global__ void k_count(const int* __restrict__ ei) {
    int e = blockIdx.x * blockDim.x + threadIdx.x;
    if (e < EE) atomicAdd(&g_deg[ei[EE + e]], 1);   // dst row of edge_index
}

// single-block exclusive scan of degrees -> rowptr, cursor; also dis = rsqrt(deg+1)
__global__ void k_scan() {
    __shared__ int part[1024];
    int tid = threadIdx.x;
    const int chunk = (NN + 1023) / 1024;           // 49
    int s = tid * chunk;
    int e = s + chunk; if (e > NN) e = NN;
    int sum = 0;
    for (int i = s; i < e; i++) sum += g_deg[i];
    part[tid] = sum;
    __syncthreads();
    for (int off = 1; off < 1024; off <<= 1) {
        int v = part[tid];
        int add = (tid >= off) ? part[tid - off] : 0;
        __syncthreads();
        part[tid] = v + add;
        __syncthreads();
    }
    int run = (tid == 0) ? 0 : part[tid - 1];
    for (int i = s; i < e; i++) {
        g_rowptr[i] = run;
        g_cursor[i] = run;
        int d = g_deg[i];
        g_dis[i] = rsqrtf((float)(d + 1));          // +1 self loop
        run += d;
    }
    if (tid == 1023) g_rowptr[NN] = run;            // == EE
}

__global__ void k_scatter(const int* __restrict__ ei) {
    int e = blockIdx.x * blockDim.x + threadIdx.x;
    if (e < EE) {
        int d = ei[EE + e];
        int pos = atomicAdd(&g_cursor[d], 1);
        g_csr[pos] = ei[e];                         // src
    }
}

// ---------------- fused GEMM: x @ [W_gcn | W_ps]  (N x 1433) x (1433 x 96) ----------------
// cols 0..63  -> g_y   = dis[row] * (x@W_gcn)
// cols 64..95 -> zsem  = x@W_ps + b_ps   (written straight to output)
__global__ __launch_bounds__(256) void k_gemm(
    const float* __restrict__ x,
    const float* __restrict__ Wg,
    const float* __restrict__ Wps,
    const float* __restrict__ bps,
    float* __restrict__ zsem)
{
    __shared__ float As[16][129];   // A transposed: As[k][row], +1 pad
    __shared__ float Bs[16][96];

    const int tid = threadIdx.x;
    const int tc  = tid & 15;       // 16 col-tiles of 6
    const int tr  = tid >> 4;       // 16 row-tiles of 8
    const int row0 = blockIdx.x * 128;

    float acc[8][6];
#pragma unroll
    for (int i = 0; i < 8; i++)
#pragma unroll
        for (int j = 0; j < 6; j++) acc[i][j] = 0.f;

    for (int kt = 0; kt < KDIM; kt += 16) {
        // load A tile (128 rows x 16 k), 8 elems/thread, coalesced over k
#pragma unroll
        for (int i = 0; i < 8; i++) {
            int idx = tid + i * 256;
            int r  = idx >> 4;
            int kk = idx & 15;
            int grow = row0 + r, gk = kt + kk;
            float v = 0.f;
            if (grow < NN && gk < KDIM) v = x[(size_t)grow * KDIM + gk];
            As[kk][r] = v;
        }
        // load B tile (16 k x 96 cols), 6 elems/thread
#pragma unroll
        for (int i = 0; i < 6; i++) {
            int idx = tid + i * 256;
            int kk = idx / 96;
            int c  = idx - kk * 96;
            int gk = kt + kk;
            float v = 0.f;
            if (gk < KDIM) v = (c < 64) ? Wg[gk * 64 + c] : Wps[gk * 32 + (c - 64)];
            Bs[kk][c] = v;
        }
        __syncthreads();
#pragma unroll
        for (int kk = 0; kk < 16; kk++) {
            float a[8], b[6];
#pragma unroll
            for (int i = 0; i < 8; i++) a[i] = As[kk][tr * 8 + i];
#pragma unroll
            for (int j = 0; j < 6; j++) b[j] = Bs[kk][tc * 6 + j];
#pragma unroll
            for (int i = 0; i < 8; i++)
#pragma unroll
                for (int j = 0; j < 6; j++)
                    acc[i][j] = fmaf(a[i], b[j], acc[i][j]);
        }
        __syncthreads();
    }

#pragma unroll
    for (int i = 0; i < 8; i++) {
        int row = row0 + tr * 8 + i;
        if (row >= NN) continue;
        float dn = g_dis[row];
#pragma unroll
        for (int j = 0; j < 6; j++) {
            int c = tc * 6 + j;
            if (c < 64) g_y[(size_t)row * 64 + c] = acc[i][j] * dn;
            else        zsem[(size_t)row * 32 + (c - 64)] = acc[i][j] + bps[c - 64];
        }
    }
}

// ---------------- gather-aggregate + full tail fusion (1 warp / node) ----------------
__global__ __launch_bounds__(256) void k_agg(
    const float* __restrict__ bg,
    const float* __restrict__ Wpt, const float* __restrict__ bpt,
    const float* __restrict__ Wcls, const float* __restrict__ bcls,
    const float* __restrict__ zsem,
    float* __restrict__ logits, float* __restrict__ anom, float* __restrict__ ztopo)
{
    __shared__ float sWpt[64 * 32];
    __shared__ float sWcls[32 * 7];
    __shared__ float sbpt[32];
    __shared__ float sbcls[8];
    __shared__ float sbg[64];
    __shared__ float sh[8][64];
    __shared__ float sz[8][32];

    int tid = threadIdx.x;
    for (int i = tid; i < 64 * 32; i += 256) sWpt[i] = Wpt[i];
    for (int i = tid; i < 32 * 7;  i += 256) sWcls[i] = Wcls[i];
    if (tid < 32) sbpt[tid] = bpt[tid];
    if (tid < 7)  sbcls[tid] = bcls[tid];
    if (tid < 64) sbg[tid] = bg[tid];
    __syncthreads();

    int warp = tid >> 5, lane = tid & 31;
    int node = blockIdx.x * 8 + warp;
    if (node >= NN) return;

    const float2* y2 = (const float2*)g_y;   // 32 float2 per row
    // self loop term + neighbor gather:  acc = y[node] + sum y[src]
    float2 acc = y2[(size_t)node * 32 + lane];
    int p = g_rowptr[node], end = g_rowptr[node + 1];
    for (; p + 4 <= end; p += 4) {
        int s0 = g_csr[p], s1 = g_csr[p + 1], s2 = g_csr[p + 2], s3 = g_csr[p + 3];
        float2 v0 = y2[(size_t)s0 * 32 + lane];
        float2 v1 = y2[(size_t)s1 * 32 + lane];
        float2 v2 = y2[(size_t)s2 * 32 + lane];
        float2 v3 = y2[(size_t)s3 * 32 + lane];
        acc.x += v0.x + v1.x + v2.x + v3.x;
        acc.y += v0.y + v1.y + v2.y + v3.y;
    }
    for (; p < end; p++) {
        int s = g_csr[p];
        float2 v = y2[(size_t)s * 32 + lane];
        acc.x += v.x; acc.y += v.y;
    }

    float dn = g_dis[node];
    float h0 = fmaxf(fmaf(dn, acc.x, sbg[2 * lane]), 0.f);
    float h1 = fmaxf(fmaf(dn, acc.y, sbg[2 * lane + 1]), 0.f);
    sh[warp][2 * lane]     = h0;
    sh[warp][2 * lane + 1] = h1;
    __syncwarp();

    // z_topo = h @ W_pt + b_pt   (lane owns one of 32 output cols)
    float z = sbpt[lane];
#pragma unroll
    for (int k = 0; k < 64; k++)
        z = fmaf(sh[warp][k], sWpt[k * 32 + lane], z);
    ztopo[(size_t)node * 32 + lane] = z;
    sz[warp][lane] = z;

    // anomaly = || z_topo - z_sem ||
    float d = z - zsem[(size_t)node * 32 + lane];
    float ss = d * d;
#pragma unroll
    for (int off = 16; off; off >>= 1) ss += __shfl_xor_sync(0xffffffffu, ss, off);
    if (lane == 0) anom[node] = sqrtf(ss);
    __syncwarp();

    // logits = z_topo @ W_cls + b_cls  (7 lanes)
    if (lane < NC) {
        float lg = sbcls[lane];
#pragma unroll
        for (int l = 0; l < 32; l++)
            lg = fmaf(sz[warp][l], sWcls[l * 7 + lane], lg);
        logits[(size_t)node * 7 + lane] = lg;
    }
}

// ---------------- launch ----------------
extern "C" void kernel_launch(void* const* d_in, const int* in_sizes, int n_in,
                              void* d_out, int out_size)
{
    const float* x    = (const float*)d_in[0];
    const int*   ei   = (const int*)  d_in[1];   // [2,E] int32 (src row, dst row)
    const float* Wg   = (const float*)d_in[2];
    const float* bg   = (const float*)d_in[3];
    const float* Wpt  = (const float*)d_in[4];
    const float* bpt  = (const float*)d_in[5];
    const float* Wps  = (const float*)d_in[6];
    const float* bps  = (const float*)d_in[7];
    const float* Wcls = (const float*)d_in[8];
    const float* bcls = (const float*)d_in[9];

    float* out    = (float*)d_out;               // [logits | anomaly | z_topo | z_sem]
    float* logits = out;
    float* anom   = out + (size_t)NN * NC;
    float* ztopo  = anom + NN;
    float* zsem   = ztopo + (size_t)NN * AD;

    k_zero_deg<<<(NN + 255) / 256, 256>>>();
    k_count  <<<(EE + 255) / 256, 256>>>(ei);
    k_scan   <<<1, 1024>>>();
    k_scatter<<<(EE + 255) / 256, 256>>>(ei);
    k_gemm   <<<(NN + 127) / 128, 256>>>(x, Wg, Wps, bps, zsem);
    k_agg    <<<(NN + 7) / 8, 256>>>(bg, Wpt, bpt, Wcls, bcls, zsem, logits, anom, ztopo);
}

// round 3
// speedup vs baseline: 1.1516x; 1.1516x over previous
#include <cuda_runtime.h>
#include <cuda_bf16.h>
#include <cstdint>
#include <math.h>

#define NN   50000
#define EE   1600000
#define KDIM 1433
#define KPAD 1440
#define HID  64
#define AD   32
#define NC   7

// ---------------- scratch (device globals; no allocs allowed) ----------------
__device__ float g_y[(size_t)NN * HID];   // dis[i] * (x @ W_gcn)  [N,64]
__device__ int   g_deg[NN];
__device__ float g_dis[NN];
__device__ int   g_rowptr[NN + 1];
__device__ int   g_cursor[NN];
__device__ int   g_csr[EE];

// ---------------- degree / CSR build ----------------
__global__ void k_zero_deg() {
    int i = blockIdx.x * blockDim.x + threadIdx.x;
    if (i < NN) g_deg[i] = 0;
}

__global__ void k_count(const int* __restrict__ ei) {
    int e = blockIdx.x * blockDim.x + threadIdx.x;
    if (e < EE) atomicAdd(&g_deg[ei[EE + e]], 1);   // dst row of edge_index
}

// single-block exclusive scan of degrees -> rowptr, cursor; also dis = rsqrt(deg+1)
__global__ void k_scan() {
    __shared__ int part[1024];
    int tid = threadIdx.x;
    const int chunk = (NN + 1023) / 1024;           // 49
    int s = tid * chunk;
    int e = s + chunk; if (e > NN) e = NN;
    int sum = 0;
    for (int i = s; i < e; i++) sum += g_deg[i];
    part[tid] = sum;
    __syncthreads();
    for (int off = 1; off < 1024; off <<= 1) {
        int v = part[tid];
        int add = (tid >= off) ? part[tid - off] : 0;
        __syncthreads();
        part[tid] = v + add;
        __syncthreads();
    }
    int run = (tid == 0) ? 0 : part[tid - 1];
    for (int i = s; i < e; i++) {
        g_rowptr[i] = run;
        g_cursor[i] = run;
        int d = g_deg[i];
        g_dis[i] = rsqrtf((float)(d + 1));          // +1 self loop
        run += d;
    }
    if (tid == 1023) g_rowptr[NN] = run;            // == EE
}

__global__ void k_scatter(const int* __restrict__ ei) {
    int e = blockIdx.x * blockDim.x + threadIdx.x;
    if (e < EE) {
        int d = ei[EE + e];
        int pos = atomicAdd(&g_cursor[d], 1);
        g_csr[pos] = ei[e];                         // src
    }
}

// ---------------- tensor-core fused GEMM: x @ [W_gcn | W_ps]  ----------------
// bf16 split precision: x*W ~= xh*Wh + xl*Wh + xh*Wl   (fp32 accumulate)
// cols 0..63  -> g_y   = dis[row] * (x@W_gcn)
// cols 64..95 -> zsem  = x@W_ps + b_ps
#define ASTRIDE 40   // bf16 units; 20 words -> conflict-free fragment loads
#define BSTRIDE 40

#define MMA_BF16(D, A0, A1, A2, A3, B0, B1)                                  \
    asm volatile(                                                            \
        "mma.sync.aligned.m16n8k16.row.col.f32.bf16.bf16.f32 "               \
        "{%0,%1,%2,%3}, {%4,%5,%6,%7}, {%8,%9}, {%0,%1,%2,%3};\n"            \
        : "+f"((D)[0]), "+f"((D)[1]), "+f"((D)[2]), "+f"((D)[3])             \
        : "r"(A0), "r"(A1), "r"(A2), "r"(A3), "r"(B0), "r"(B1))

__global__ __launch_bounds__(256, 2) void k_gemm(
    const float* __restrict__ x,
    const float* __restrict__ Wg,
    const float* __restrict__ Wps,
    const float* __restrict__ bps,
    float* __restrict__ zsem)
{
    __shared__ __nv_bfloat16 Ah[128 * ASTRIDE];
    __shared__ __nv_bfloat16 Al[128 * ASTRIDE];
    __shared__ __nv_bfloat16 Bh[96 * BSTRIDE];   // n-major: Bh[n][k]
    __shared__ __nv_bfloat16 Bl[96 * BSTRIDE];

    const int tid    = threadIdx.x;
    const int lane   = tid & 31;
    const int wid    = tid >> 5;
    const int warp_m = wid >> 2;      // 0..1  (64 rows each)
    const int warp_n = wid & 3;       // 0..3  (24 cols each)
    const int row0   = blockIdx.x * 128;

    float acc[4][3][4];
#pragma unroll
    for (int i = 0; i < 4; i++)
#pragma unroll
        for (int j = 0; j < 3; j++)
#pragma unroll
            for (int q = 0; q < 4; q++) acc[i][j][q] = 0.f;

    const int a_r  = tid >> 5;        // 0..7 (row within pass)
    const int a_k  = tid & 31;        // k within chunk

    for (int kt = 0; kt < KPAD; kt += 32) {
        // ---- load A tile: 128 rows x 32 k, fp32 -> bf16 hi/lo ----
#pragma unroll
        for (int i = 0; i < 16; i++) {
            int r    = i * 8 + a_r;
            int grow = row0 + r;
            int gk   = kt + a_k;
            float v  = 0.f;
            if (grow < NN && gk < KDIM) v = x[(size_t)grow * KDIM + gk];
            __nv_bfloat16 h = __float2bfloat16(v);
            __nv_bfloat16 l = __float2bfloat16(v - __bfloat162float(h));
            Ah[r * ASTRIDE + a_k] = h;
            Al[r * ASTRIDE + a_k] = l;
        }
        // ---- load B tile: 32 k x 96 cols -> n-major bf16 hi/lo ----
#pragma unroll
        for (int i = 0; i < 12; i++) {
            int idx = tid + i * 256;
            int kk  = idx / 96;
            int c   = idx - kk * 96;
            int gk  = kt + kk;
            float v = 0.f;
            if (gk < KDIM) v = (c < 64) ? Wg[gk * 64 + c] : Wps[gk * 32 + (c - 64)];
            __nv_bfloat16 h = __float2bfloat16(v);
            __nv_bfloat16 l = __float2bfloat16(v - __bfloat162float(h));
            Bh[c * BSTRIDE + kk] = h;
            Bl[c * BSTRIDE + kk] = l;
        }
        __syncthreads();

        // ---- compute: 2 k-steps of 16 ----
#pragma unroll
        for (int ks = 0; ks < 32; ks += 16) {
            const int kq = ks + (lane & 3) * 2;
            // B fragments for the 3 n-tiles
            unsigned int bh[3][2], bl[3][2];
#pragma unroll
            for (int nt = 0; nt < 3; nt++) {
                int n = warp_n * 24 + nt * 8 + (lane >> 2);
                const __nv_bfloat16* pbh = &Bh[n * BSTRIDE + kq];
                const __nv_bfloat16* pbl = &Bl[n * BSTRIDE + kq];
                bh[nt][0] = *(const unsigned int*)pbh;
                bh[nt][1] = *(const unsigned int*)(pbh + 8);
                bl[nt][0] = *(const unsigned int*)pbl;
                bl[nt][1] = *(const unsigned int*)(pbl + 8);
            }
#pragma unroll
            for (int mt = 0; mt < 4; mt++) {
                int r = warp_m * 64 + mt * 16 + (lane >> 2);
                const __nv_bfloat16* pah = &Ah[r * ASTRIDE + kq];
                const __nv_bfloat16* pal = &Al[r * ASTRIDE + kq];
                unsigned int ah0 = *(const unsigned int*)pah;
                unsigned int ah1 = *(const unsigned int*)(pah + 8 * ASTRIDE);
                unsigned int ah2 = *(const unsigned int*)(pah + 8);
                unsigned int ah3 = *(const unsigned int*)(pah + 8 * ASTRIDE + 8);
                unsigned int al0 = *(const unsigned int*)pal;
                unsigned int al1 = *(const unsigned int*)(pal + 8 * ASTRIDE);
                unsigned int al2 = *(const unsigned int*)(pal + 8);
                unsigned int al3 = *(const unsigned int*)(pal + 8 * ASTRIDE + 8);
#pragma unroll
                for (int nt = 0; nt < 3; nt++) {
                    MMA_BF16(acc[mt][nt], ah0, ah1, ah2, ah3, bh[nt][0], bh[nt][1]);
                    MMA_BF16(acc[mt][nt], al0, al1, al2, al3, bh[nt][0], bh[nt][1]);
                    MMA_BF16(acc[mt][nt], ah0, ah1, ah2, ah3, bl[nt][0], bl[nt][1]);
                }
            }
        }
        __syncthreads();
    }

    // ---- epilogue ----
#pragma unroll
    for (int mt = 0; mt < 4; mt++) {
#pragma unroll
        for (int nt = 0; nt < 3; nt++) {
            int row = row0 + warp_m * 64 + mt * 16 + (lane >> 2);
            int col = warp_n * 24 + nt * 8 + (lane & 3) * 2;
            const float* d = acc[mt][nt];
#pragma unroll
            for (int half = 0; half < 2; half++) {
                int rr = row + half * 8;
                if (rr >= NN) continue;
                float v0 = d[half * 2], v1 = d[half * 2 + 1];
                if (col < 64) {
                    float f = g_dis[rr];
                    g_y[(size_t)rr * 64 + col]     = v0 * f;
                    g_y[(size_t)rr * 64 + col + 1] = v1 * f;
                } else {
                    zsem[(size_t)rr * 32 + (col - 64)]     = v0 + bps[col - 64];
                    zsem[(size_t)rr * 32 + (col - 64) + 1] = v1 + bps[col - 63];
                }
            }
        }
    }
}

// ---------------- gather-aggregate + full tail fusion (1 warp / node) ----------------
__global__ __launch_bounds__(256) void k_agg(
    const float* __restrict__ bg,
    const float* __restrict__ Wpt, const float* __restrict__ bpt,
    const float* __restrict__ Wcls, const float* __restrict__ bcls,
    const float* __restrict__ zsem,
    float* __restrict__ logits, float* __restrict__ anom, float* __restrict__ ztopo)
{
    __shared__ float sWpt[64 * 32];
    __shared__ float sWcls[32 * 7];
    __shared__ float sbpt[32];
    __shared__ float sbcls[8];
    __shared__ float sbg[64];
    __shared__ float sh[8][64];
    __shared__ float sz[8][32];

    int tid = threadIdx.x;
    for (int i = tid; i < 64 * 32; i += 256) sWpt[i] = Wpt[i];
    for (int i = tid; i < 32 * 7;  i += 256) sWcls[i] = Wcls[i];
    if (tid < 32) sbpt[tid] = bpt[tid];
    if (tid < 7)  sbcls[tid] = bcls[tid];
    if (tid < 64) sbg[tid] = bg[tid];
    __syncthreads();

    int warp = tid >> 5, lane = tid & 31;
    int node = blockIdx.x * 8 + warp;
    if (node >= NN) return;

    const float2* y2 = (const float2*)g_y;   // 32 float2 per row
    // self loop term + neighbor gather:  acc = y[node] + sum y[src]
    float2 acc = y2[(size_t)node * 32 + lane];
    int p = g_rowptr[node], end = g_rowptr[node + 1];
    for (; p + 4 <= end; p += 4) {
        int s0 = g_csr[p], s1 = g_csr[p + 1], s2 = g_csr[p + 2], s3 = g_csr[p + 3];
        float2 v0 = y2[(size_t)s0 * 32 + lane];
        float2 v1 = y2[(size_t)s1 * 32 + lane];
        float2 v2 = y2[(size_t)s2 * 32 + lane];
        float2 v3 = y2[(size_t)s3 * 32 + lane];
        acc.x += v0.x + v1.x + v2.x + v3.x;
        acc.y += v0.y + v1.y + v2.y + v3.y;
    }
    for (; p < end; p++) {
        int s = g_csr[p];
        float2 v = y2[(size_t)s * 32 + lane];
        acc.x += v.x; acc.y += v.y;
    }

    float dn = g_dis[node];
    float h0 = fmaxf(fmaf(dn, acc.x, sbg[2 * lane]), 0.f);
    float h1 = fmaxf(fmaf(dn, acc.y, sbg[2 * lane + 1]), 0.f);
    sh[warp][2 * lane]     = h0;
    sh[warp][2 * lane + 1] = h1;
    __syncwarp();

    // z_topo = h @ W_pt + b_pt   (lane owns one of 32 output cols)
    float z = sbpt[lane];
#pragma unroll
    for (int k = 0; k < 64; k++)
        z = fmaf(sh[warp][k], sWpt[k * 32 + lane], z);
    ztopo[(size_t)node * 32 + lane] = z;
    sz[warp][lane] = z;

    // anomaly = || z_topo - z_sem ||
    float d = z - zsem[(size_t)node * 32 + lane];
    float ss = d * d;
#pragma unroll
    for (int off = 16; off; off >>= 1) ss += __shfl_xor_sync(0xffffffffu, ss, off);
    if (lane == 0) anom[node] = sqrtf(ss);
    __syncwarp();

    // logits = z_topo @ W_cls + b_cls  (7 lanes)
    if (lane < NC) {
        float lg = sbcls[lane];
#pragma unroll
        for (int l = 0; l < 32; l++)
            lg = fmaf(sz[warp][l], sWcls[l * 7 + lane], lg);
        logits[(size_t)node * 7 + lane] = lg;
    }
}

// ---------------- launch ----------------
extern "C" void kernel_launch(void* const* d_in, const int* in_sizes, int n_in,
                              void* d_out, int out_size)
{
    const float* x    = (const float*)d_in[0];
    const int*   ei   = (const int*)  d_in[1];   // [2,E] int32 (src row, dst row)
    const float* Wg   = (const float*)d_in[2];
    const float* bg   = (const float*)d_in[3];
    const float* Wpt  = (const float*)d_in[4];
    const float* bpt  = (const float*)d_in[5];
    const float* Wps  = (const float*)d_in[6];
    const float* bps  = (const float*)d_in[7];
    const float* Wcls = (const float*)d_in[8];
    const float* bcls = (const float*)d_in[9];

    float* out    = (float*)d_out;               // [logits | anomaly | z_topo | z_sem]
    float* logits = out;
    float* anom   = out + (size_t)NN * NC;
    float* ztopo  = anom + NN;
    float* zsem   = ztopo + (size_t)NN * AD;

    k_zero_deg<<<(NN + 255) / 256, 256>>>();
    k_count  <<<(EE + 255) / 256, 256>>>(ei);
    k_scan   <<<1, 1024>>>();
    k_scatter<<<(EE + 255) / 256, 256>>>(ei);
    k_gemm   <<<(NN + 127) / 128, 256>>>(x, Wg, Wps, bps, zsem);
    k_agg    <<<(NN + 7) / 8, 256>>>(bg, Wpt, bpt, Wcls, bcls, zsem, logits, anom, ztopo);
}

// round 5
// speedup vs baseline: 2.6524x; 2.3033x over previous
#include <cuda_runtime.h>
#include <cuda_fp16.h>
#include <cstdint>
#include <math.h>

#define NN   50000
#define EE   1600000
#define KDIM 1433
#define KP2  1440        // 45 * 32
#define NC   7
#define NITER 45

// ---------------- scratch (device globals; no allocs allowed) ----------------
__device__ float g_y[(size_t)NN * 64];   // dis[i] * (x @ W_gcn)  [N,64]
__device__ int   g_deg[NN];
__device__ float g_dis[NN];
__device__ int   g_rowptr[NN + 1];
__device__ int   g_cursor[NN];
__device__ int   g_csr[EE];
__device__ __half g_Wh[96 * KP2];        // n-major [96][1440] fp16 of [Wg|Wps]

// ---------------- degree / CSR build ----------------
__global__ void k_zero_deg() {
    int i = blockIdx.x * blockDim.x + threadIdx.x;
    if (i < NN) g_deg[i] = 0;
}

__global__ void k_count(const int* __restrict__ ei) {
    int e = blockIdx.x * blockDim.x + threadIdx.x;
    if (e < EE) atomicAdd(&g_deg[ei[EE + e]], 1);
}

__global__ void k_scan() {
    __shared__ int part[1024];
    int tid = threadIdx.x;
    const int chunk = (NN + 1023) / 1024;
    int s = tid * chunk;
    int e = s + chunk; if (e > NN) e = NN;
    int sum = 0;
    for (int i = s; i < e; i++) sum += g_deg[i];
    part[tid] = sum;
    __syncthreads();
    for (int off = 1; off < 1024; off <<= 1) {
        int v = part[tid];
        int add = (tid >= off) ? part[tid - off] : 0;
        __syncthreads();
        part[tid] = v + add;
        __syncthreads();
    }
    int run = (tid == 0) ? 0 : part[tid - 1];
    for (int i = s; i < e; i++) {
        g_rowptr[i] = run;
        g_cursor[i] = run;
        int d = g_deg[i];
        g_dis[i] = rsqrtf((float)(d + 1));
        run += d;
    }
    if (tid == 1023) g_rowptr[NN] = run;
}

__global__ void k_scatter(const int* __restrict__ ei) {
    int e = blockIdx.x * blockDim.x + threadIdx.x;
    if (e < EE) {
        int d = ei[EE + e];
        int pos = atomicAdd(&g_cursor[d], 1);
        g_csr[pos] = ei[e];
    }
}

// ---------------- pre-convert W = [W_gcn | W_ps] to n-major fp16 ----------------
__global__ void k_convB(const float* __restrict__ Wg, const float* __restrict__ Wps) {
    int t = blockIdx.x * blockDim.x + threadIdx.x;
    if (t >= 96 * KP2) return;
    int n = t / KP2, k = t - n * KP2;
    float v = 0.f;
    if (k < KDIM) v = (n < 64) ? Wg[k * 64 + n] : Wps[k * 32 + (n - 64)];
    g_Wh[t] = __float2half_rn(v);
}

// ---------------- tensor GEMM: x @ [W_gcn | W_ps], fp16 2-term split ----------------
// x ~= xh + xl (both fp16, fp32-exact to ~2^-22). result = xh*W + xl*W (fp32 accum).
// M-tile 128, N = 96, k-tile 32. Double-buffered smem, reg-prefetch pipeline.
#define ASTRIDE 40
#define STG_AH 0
#define STG_AL 10240
#define STG_B  20480
#define STG_SZ 28160
#define SMEM_GEMM (2 * STG_SZ)

#define MMA_F16(D, A0, A1, A2, A3, B0, B1)                                   \
    asm volatile(                                                            \
        "mma.sync.aligned.m16n8k16.row.col.f32.f16.f16.f32 "                 \
        "{%0,%1,%2,%3}, {%4,%5,%6,%7}, {%8,%9}, {%0,%1,%2,%3};\n"            \
        : "+f"((D)[0]), "+f"((D)[1]), "+f"((D)[2]), "+f"((D)[3])             \
        : "r"(A0), "r"(A1), "r"(A2), "r"(A3), "r"(B0), "r"(B1))

__global__ __launch_bounds__(256, 2) void k_gemm(
    const float* __restrict__ x,
    const float* __restrict__ bps,
    float* __restrict__ zsem)
{
    extern __shared__ char sm[];
    const int tid    = threadIdx.x;
    const int lane   = tid & 31;
    const int wid    = tid >> 5;
    const int warp_m = wid >> 2;      // 0..1  (64 rows)
    const int warp_n = wid & 3;       // 0..3  (24 cols)
    const int row0   = blockIdx.x * 128;

    float acc[4][3][4];
#pragma unroll
    for (int i = 0; i < 4; i++)
#pragma unroll
        for (int j = 0; j < 3; j++)
#pragma unroll
            for (int q = 0; q < 4; q++) acc[i][j][q] = 0.f;

    float fA[16];
    uint4 fB[2];
    const int ar = tid >> 4;          // base row (0..15), +16 per task step
    const int ac = (tid & 15) * 2;    // k-pair column

    // ---- tile load: gmem -> regs ----
    auto ldg_tile = [&](int j) {
        const int kt = j * 32;
#pragma unroll
        for (int i = 0; i < 8; i++) {
            int r = i * 16 + ar;
            int grow = row0 + r, gk = kt + ac;
            float f0 = 0.f, f1 = 0.f;
            if (grow < NN) {
                const float* xp = x + (size_t)grow * KDIM + gk;
                if (gk < KDIM)     f0 = __ldg(xp);
                if (gk + 1 < KDIM) f1 = __ldg(xp + 1);
            }
            fA[2 * i] = f0; fA[2 * i + 1] = f1;
        }
        {
            int t0 = tid;                       // tasks 0..255
            int n = t0 >> 2, q = t0 & 3;
            fB[0] = *(const uint4*)((const char*)g_Wh + ((size_t)n * KP2 + kt) * 2 + q * 16);
            if (tid < 128) {
                int t1 = tid + 256;             // tasks 256..383
                int n1 = t1 >> 2, q1 = t1 & 3;
                fB[1] = *(const uint4*)((const char*)g_Wh + ((size_t)n1 * KP2 + kt) * 2 + q1 * 16);
            }
        }
    };

    // ---- tile store: regs -> smem (with fp32->fp16 hi/lo split for A) ----
    auto sts_tile = [&](int buf) {
        char* base = sm + buf * STG_SZ;
        __half* Ah = (__half*)(base + STG_AH);
        __half* Al = (__half*)(base + STG_AL);
        __half* Bs = (__half*)(base + STG_B);
#pragma unroll
        for (int i = 0; i < 8; i++) {
            int r = i * 16 + ar;
            float f0 = fA[2 * i], f1 = fA[2 * i + 1];
            __half2 h2 = __floats2half2_rn(f0, f1);
            __half2 l2 = __floats2half2_rn(f0 - __low2float(h2), f1 - __high2float(h2));
            *(uint32_t*)&Ah[r * ASTRIDE + ac] = *(uint32_t*)&h2;
            *(uint32_t*)&Al[r * ASTRIDE + ac] = *(uint32_t*)&l2;
        }
        {
            int n = tid >> 2, q = tid & 3;
            *(uint4*)&Bs[n * ASTRIDE + q * 8] = fB[0];
            if (tid < 128) {
                int t1 = tid + 256;
                int n1 = t1 >> 2, q1 = t1 & 3;
                *(uint4*)&Bs[n1 * ASTRIDE + q1 * 8] = fB[1];
            }
        }
    };

    // ---- compute one k-tile from smem buf ----
    auto compute = [&](int buf) {
        char* base = sm + buf * STG_SZ;
        const __half* Ah = (const __half*)(base + STG_AH);
        const __half* Al = (const __half*)(base + STG_AL);
        const __half* Bs = (const __half*)(base + STG_B);
#pragma unroll
        for (int ks = 0; ks < 32; ks += 16) {
            const int kq = ks + (lane & 3) * 2;
            uint32_t bb[3][2];
#pragma unroll
            for (int nt = 0; nt < 3; nt++) {
                int n = warp_n * 24 + nt * 8 + (lane >> 2);
                const __half* pb = &Bs[n * ASTRIDE + kq];
                bb[nt][0] = *(const uint32_t*)pb;
                bb[nt][1] = *(const uint32_t*)(pb + 8);
            }
#pragma unroll
            for (int mt = 0; mt < 4; mt++) {
                int r = warp_m * 64 + mt * 16 + (lane >> 2);
                const __half* ph = &Ah[r * ASTRIDE + kq];
                const __half* pl = &Al[r * ASTRIDE + kq];
                uint32_t ah0 = *(const uint32_t*)ph;
                uint32_t ah1 = *(const uint32_t*)(ph + 8 * ASTRIDE);
                uint32_t ah2 = *(const uint32_t*)(ph + 8);
                uint32_t ah3 = *(const uint32_t*)(ph + 8 * ASTRIDE + 8);
                uint32_t al0 = *(const uint32_t*)pl;
                uint32_t al1 = *(const uint32_t*)(pl + 8 * ASTRIDE);
                uint32_t al2 = *(const uint32_t*)(pl + 8);
                uint32_t al3 = *(const uint32_t*)(pl + 8 * ASTRIDE + 8);
#pragma unroll
                for (int nt = 0; nt < 3; nt++) {
                    MMA_F16(acc[mt][nt], ah0, ah1, ah2, ah3, bb[nt][0], bb[nt][1]);
                    MMA_F16(acc[mt][nt], al0, al1, al2, al3, bb[nt][0], bb[nt][1]);
                }
            }
        }
    };

    // ---- pipeline: 1 sync/iter, LDG(j) overlaps compute(j-1) ----
    ldg_tile(0);
    sts_tile(0);
    __syncthreads();
    for (int j = 1; j < NITER; j++) {
        ldg_tile(j);
        compute((j - 1) & 1);
        sts_tile(j & 1);
        __syncthreads();
    }
    compute((NITER - 1) & 1);

    // ---- epilogue ----
#pragma unroll
    for (int mt = 0; mt < 4; mt++) {
#pragma unroll
        for (int nt = 0; nt < 3; nt++) {
            int row = row0 + warp_m * 64 + mt * 16 + (lane >> 2);
            int col = warp_n * 24 + nt * 8 + (lane & 3) * 2;
            const float* d = acc[mt][nt];
#pragma unroll
            for (int half = 0; half < 2; half++) {
                int rr = row + half * 8;
                if (rr >= NN) continue;
                float v0 = d[half * 2], v1 = d[half * 2 + 1];
                if (col < 64) {
                    float f = g_dis[rr];
                    g_y[(size_t)rr * 64 + col]     = v0 * f;
                    g_y[(size_t)rr * 64 + col + 1] = v1 * f;
                } else {
                    zsem[(size_t)rr * 32 + (col - 64)]     = v0 + bps[col - 64];
                    zsem[(size_t)rr * 32 + (col - 64) + 1] = v1 + bps[col - 63];
                }
            }
        }
    }
}

// ---------------- gather-aggregate + full tail fusion (1 warp / node) ----------------
__global__ __launch_bounds__(256) void k_agg(
    const float* __restrict__ bg,
    const float* __restrict__ Wpt, const float* __restrict__ bpt,
    const float* __restrict__ Wcls, const float* __restrict__ bcls,
    const float* __restrict__ zsem,
    float* __restrict__ logits, float* __restrict__ anom, float* __restrict__ ztopo)
{
    __shared__ float sWpt[64 * 32];
    __shared__ float sWcls[32 * 7];
    __shared__ float sbpt[32];
    __shared__ float sbcls[8];
    __shared__ float sbg[64];
    __shared__ float sh[8][64];
    __shared__ float sz[8][32];

    int tid = threadIdx.x;
    for (int i = tid; i < 64 * 32; i += 256) sWpt[i] = Wpt[i];
    for (int i = tid; i < 32 * 7;  i += 256) sWcls[i] = Wcls[i];
    if (tid < 32) sbpt[tid] = bpt[tid];
    if (tid < 7)  sbcls[tid] = bcls[tid];
    if (tid < 64) sbg[tid] = bg[tid];
    __syncthreads();

    int warp = tid >> 5, lane = tid & 31;
    int node = blockIdx.x * 8 + warp;
    if (node >= NN) return;

    const float2* y2 = (const float2*)g_y;
    float2 acc = y2[(size_t)node * 32 + lane];
    int p = g_rowptr[node], end = g_rowptr[node + 1];
    for (; p + 4 <= end; p += 4) {
        int s0 = g_csr[p], s1 = g_csr[p + 1], s2 = g_csr[p + 2], s3 = g_csr[p + 3];
        float2 v0 = y2[(size_t)s0 * 32 + lane];
        float2 v1 = y2[(size_t)s1 * 32 + lane];
        float2 v2 = y2[(size_t)s2 * 32 + lane];
        float2 v3 = y2[(size_t)s3 * 32 + lane];
        acc.x += v0.x + v1.x + v2.x + v3.x;
        acc.y += v0.y + v1.y + v2.y + v3.y;
    }
    for (; p < end; p++) {
        int s = g_csr[p];
        float2 v = y2[(size_t)s * 32 + lane];
        acc.x += v.x; acc.y += v.y;
    }

    float dn = g_dis[node];
    float h0 = fmaxf(fmaf(dn, acc.x, sbg[2 * lane]), 0.f);
    float h1 = fmaxf(fmaf(dn, acc.y, sbg[2 * lane + 1]), 0.f);
    sh[warp][2 * lane]     = h0;
    sh[warp][2 * lane + 1] = h1;
    __syncwarp();

    float z = sbpt[lane];
#pragma unroll
    for (int k = 0; k < 64; k++)
        z = fmaf(sh[warp][k], sWpt[k * 32 + lane], z);
    ztopo[(size_t)node * 32 + lane] = z;
    sz[warp][lane] = z;

    float d = z - zsem[(size_t)node * 32 + lane];
    float ss = d * d;
#pragma unroll
    for (int off = 16; off; off >>= 1) ss += __shfl_xor_sync(0xffffffffu, ss, off);
    if (lane == 0) anom[node] = sqrtf(ss);
    __syncwarp();

    if (lane < NC) {
        float lg = sbcls[lane];
#pragma unroll
        for (int l = 0; l < 32; l++)
            lg = fmaf(sz[warp][l], sWcls[l * 7 + lane], lg);
        logits[(size_t)node * 7 + lane] = lg;
    }
}

// ---------------- launch ----------------
extern "C" void kernel_launch(void* const* d_in, const int* in_sizes, int n_in,
                              void* d_out, int out_size)
{
    const float* x    = (const float*)d_in[0];
    const int*   ei   = (const int*)  d_in[1];
    const float* Wg   = (const float*)d_in[2];
    const float* bg   = (const float*)d_in[3];
    const float* Wpt  = (const float*)d_in[4];
    const float* bpt  = (const float*)d_in[5];
    const float* Wps  = (const float*)d_in[6];
    const float* bps  = (const float*)d_in[7];
    const float* Wcls = (const float*)d_in[8];
    const float* bcls = (const float*)d_in[9];

    float* out    = (float*)d_out;               // [logits | anomaly | z_topo | z_sem]
    float* logits = out;
    float* anom   = out + (size_t)NN * NC;
    float* ztopo  = anom + NN;
    float* zsem   = ztopo + (size_t)NN * 32;

    cudaFuncSetAttribute(k_gemm, cudaFuncAttributeMaxDynamicSharedMemorySize, SMEM_GEMM);

    k_zero_deg<<<(NN + 255) / 256, 256>>>();
    k_count  <<<(EE + 255) / 256, 256>>>(ei);
    k_scan   <<<1, 1024>>>();
    k_scatter<<<(EE + 255) / 256, 256>>>(ei);
    k_convB  <<<(96 * KP2 + 255) / 256, 256>>>(Wg, Wps);
    k_gemm   <<<(NN + 127) / 128, 256, SMEM_GEMM>>>(x, bps, zsem);
    k_agg    <<<(NN + 7) / 8, 256>>>(bg, Wpt, bpt, Wcls, bcls, zsem, logits, anom, ztopo);
}

// round 6
// speedup vs baseline: 4.3765x; 1.6500x over previous
#include <cuda_runtime.h>
#include <cuda_fp16.h>
#include <cstdint>
#include <math.h>

#define NN   50000
#define EE   1600000
#define KDIM 1433
#define KP2  1440        // 45 * 32
#define NC   7
#define NITER 45

// ---------------- scratch (device globals; no allocs allowed) ----------------
__device__ float g_y[(size_t)NN * 64];   // dis[i] * (x @ W_gcn)  [N,64]
__device__ int   g_deg[NN];
__device__ float g_dis[NN];
__device__ int   g_rowptr[NN + 1];
__device__ int   g_cursor[NN];
__device__ int   g_csr[EE];
__device__ int   g_bsum[256];
__device__ int   g_boff[256];
__device__ __half g_Wh[96 * KP2];        // n-major [96][1440] fp16 of [Wg|Wps]

// ---------------- degree / CSR build ----------------
__global__ void k_zero_deg() {
    int i = blockIdx.x * blockDim.x + threadIdx.x;
    if (i < NN) g_deg[i] = 0;
}

__global__ void k_count(const int* __restrict__ ei) {
    int e4 = blockIdx.x * blockDim.x + threadIdx.x;
    if (e4 < EE / 4) {
        int4 d = ((const int4*)(ei + EE))[e4];
        atomicAdd(&g_deg[d.x], 1);
        atomicAdd(&g_deg[d.y], 1);
        atomicAdd(&g_deg[d.z], 1);
        atomicAdd(&g_deg[d.w], 1);
    }
}

// 3-phase exclusive scan over g_deg -> g_rowptr / g_cursor, plus dis
__global__ void k_scanA() {
    __shared__ int s[256];
    int t = threadIdx.x, b = blockIdx.x;
    int i = b * 256 + t;
    int v = (i < NN) ? g_deg[i] : 0;
    s[t] = v;
    __syncthreads();
#pragma unroll
    for (int off = 1; off < 256; off <<= 1) {
        int u = s[t];
        int add = (t >= off) ? s[t - off] : 0;
        __syncthreads();
        s[t] = u + add;
        __syncthreads();
    }
    if (i < NN) g_rowptr[i] = s[t] - v;     // exclusive-within-block
    if (t == 255) g_bsum[b] = s[255];
}

__global__ void k_scanB() {
    __shared__ int s[256];
    int t = threadIdx.x;
    int v = (t < 196) ? g_bsum[t] : 0;
    s[t] = v;
    __syncthreads();
#pragma unroll
    for (int off = 1; off < 256; off <<= 1) {
        int u = s[t];
        int add = (t >= off) ? s[t - off] : 0;
        __syncthreads();
        s[t] = u + add;
        __syncthreads();
    }
    g_boff[t] = s[t] - v;
    if (t == 255) g_rowptr[NN] = s[255];    // == EE
}

__global__ void k_scanC() {
    int i = blockIdx.x * blockDim.x + threadIdx.x;
    if (i < NN) {
        int r = g_rowptr[i] + g_boff[blockIdx.x];
        g_rowptr[i] = r;
        g_cursor[i] = r;
        g_dis[i] = rsqrtf((float)(g_deg[i] + 1));
    }
}

__global__ void k_scatter(const int* __restrict__ ei) {
    int e = blockIdx.x * blockDim.x + threadIdx.x;
    if (e < EE) {
        int d = ei[EE + e];
        int pos = atomicAdd(&g_cursor[d], 1);
        g_csr[pos] = ei[e];
    }
}

// ---------------- pre-convert W = [W_gcn | W_ps] to n-major fp16 ----------------
__global__ void k_convB(const float* __restrict__ Wg, const float* __restrict__ Wps) {
    int t = blockIdx.x * blockDim.x + threadIdx.x;
    if (t >= 96 * KP2) return;
    int n = t / KP2, k = t - n * KP2;
    float v = 0.f;
    if (k < KDIM) v = (n < 64) ? Wg[k * 64 + n] : Wps[k * 32 + (n - 64)];
    g_Wh[t] = __float2half_rn(v);
}

// ---------------- tensor GEMM: x @ [W_gcn | W_ps], single-term fp16 ----------------
// M-tile 128, N = 96, k-tile 32. Double-buffered smem, reg-prefetch pipeline,
// ldmatrix fragment loads (stride-40-half rows are conflict-free).
#define ASTRIDE 40
#define STG_AH 0
#define STG_B  10240
#define STG_SZ 17920
#define SMEM_GEMM (2 * STG_SZ)

#define MMA_F16(D, A0, A1, A2, A3, B0, B1)                                   \
    asm volatile(                                                            \
        "mma.sync.aligned.m16n8k16.row.col.f32.f16.f16.f32 "                 \
        "{%0,%1,%2,%3}, {%4,%5,%6,%7}, {%8,%9}, {%0,%1,%2,%3};\n"            \
        : "+f"((D)[0]), "+f"((D)[1]), "+f"((D)[2]), "+f"((D)[3])             \
        : "r"(A0), "r"(A1), "r"(A2), "r"(A3), "r"(B0), "r"(B1))

#define LDSM_X4(R0, R1, R2, R3, ADDR)                                        \
    asm volatile("ldmatrix.sync.aligned.m8n8.x4.shared.b16 {%0,%1,%2,%3}, [%4];" \
        : "=r"(R0), "=r"(R1), "=r"(R2), "=r"(R3) : "r"(ADDR))

#define LDSM_X2(R0, R1, ADDR)                                                \
    asm volatile("ldmatrix.sync.aligned.m8n8.x2.shared.b16 {%0,%1}, [%2];"   \
        : "=r"(R0), "=r"(R1) : "r"(ADDR))

__global__ __launch_bounds__(256, 2) void k_gemm(
    const float* __restrict__ x,
    const float* __restrict__ bps,
    float* __restrict__ zsem)
{
    extern __shared__ char sm[];
    const uint32_t smb = (uint32_t)__cvta_generic_to_shared(sm);
    const int tid    = threadIdx.x;
    const int lane   = tid & 31;
    const int wid    = tid >> 5;
    const int warp_m = wid >> 2;      // 0..1  (64 rows)
    const int warp_n = wid & 3;       // 0..3  (24 cols)
    const int row0   = blockIdx.x * 128;

    float acc[4][3][4];
#pragma unroll
    for (int i = 0; i < 4; i++)
#pragma unroll
        for (int j = 0; j < 3; j++)
#pragma unroll
            for (int q = 0; q < 4; q++) acc[i][j][q] = 0.f;

    float fA[16];
    uint4 fB[2];
    const int ar = tid >> 4;          // base row (0..15), +16 per task step
    const int ac = (tid & 15) * 2;    // k-pair column

    // ldmatrix lane-address components (halves)
    const int a_loff = (warp_m * 64 + (lane & 15)) * ASTRIDE + (lane >> 4) * 8;
    const int b_loff = (warp_n * 24 + (lane & 7)) * ASTRIDE + ((lane >> 3) & 1) * 8;

    auto ldg_tile = [&](int j) {
        const int kt = j * 32;
#pragma unroll
        for (int i = 0; i < 8; i++) {
            int r = i * 16 + ar;
            int grow = row0 + r, gk = kt + ac;
            float f0 = 0.f, f1 = 0.f;
            if (grow < NN) {
                const float* xp = x + (size_t)grow * KDIM + gk;
                if (gk < KDIM)     f0 = __ldg(xp);
                if (gk + 1 < KDIM) f1 = __ldg(xp + 1);
            }
            fA[2 * i] = f0; fA[2 * i + 1] = f1;
        }
        {
            int n = tid >> 2, q = tid & 3;
            fB[0] = *(const uint4*)((const char*)g_Wh + ((size_t)n * KP2 + kt) * 2 + q * 16);
            if (tid < 128) {
                int t1 = tid + 256;
                int n1 = t1 >> 2, q1 = t1 & 3;
                fB[1] = *(const uint4*)((const char*)g_Wh + ((size_t)n1 * KP2 + kt) * 2 + q1 * 16);
            }
        }
    };

    auto sts_tile = [&](int buf) {
        char* base = sm + buf * STG_SZ;
        __half* Ah = (__half*)(base + STG_AH);
        __half* Bs = (__half*)(base + STG_B);
#pragma unroll
        for (int i = 0; i < 8; i++) {
            int r = i * 16 + ar;
            __half2 h2 = __floats2half2_rn(fA[2 * i], fA[2 * i + 1]);
            *(uint32_t*)&Ah[r * ASTRIDE + ac] = *(uint32_t*)&h2;
        }
        {
            int n = tid >> 2, q = tid & 3;
            *(uint4*)&Bs[n * ASTRIDE + q * 8] = fB[0];
            if (tid < 128) {
                int t1 = tid + 256;
                int n1 = t1 >> 2, q1 = t1 & 3;
                *(uint4*)&Bs[n1 * ASTRIDE + q1 * 8] = fB[1];
            }
        }
    };

    auto compute = [&](int buf) {
        uint32_t ahb = smb + buf * STG_SZ + STG_AH + a_loff * 2;
        uint32_t bsb = smb + buf * STG_SZ + STG_B  + b_loff * 2;
#pragma unroll
        for (int ks = 0; ks < 32; ks += 16) {
            uint32_t bb[3][2];
#pragma unroll
            for (int nt = 0; nt < 3; nt++)
                LDSM_X2(bb[nt][0], bb[nt][1], bsb + (nt * 8 * ASTRIDE + ks) * 2);
#pragma unroll
            for (int mt = 0; mt < 4; mt++) {
                uint32_t a0, a1, a2, a3;
                LDSM_X4(a0, a1, a2, a3, ahb + (mt * 16 * ASTRIDE + ks) * 2);
#pragma unroll
                for (int nt = 0; nt < 3; nt++)
                    MMA_F16(acc[mt][nt], a0, a1, a2, a3, bb[nt][0], bb[nt][1]);
            }
        }
    };

    // ---- pipeline: 1 sync/iter, LDG(j) overlaps compute(j-1) ----
    ldg_tile(0);
    sts_tile(0);
    __syncthreads();
    for (int j = 1; j < NITER; j++) {
        ldg_tile(j);
        compute((j - 1) & 1);
        sts_tile(j & 1);
        __syncthreads();
    }
    compute((NITER - 1) & 1);

    // ---- epilogue ----
#pragma unroll
    for (int mt = 0; mt < 4; mt++) {
#pragma unroll
        for (int nt = 0; nt < 3; nt++) {
            int row = row0 + warp_m * 64 + mt * 16 + (lane >> 2);
            int col = warp_n * 24 + nt * 8 + (lane & 3) * 2;
            const float* d = acc[mt][nt];
#pragma unroll
            for (int half = 0; half < 2; half++) {
                int rr = row + half * 8;
                if (rr >= NN) continue;
                float v0 = d[half * 2], v1 = d[half * 2 + 1];
                if (col < 64) {
                    float f = g_dis[rr];
                    g_y[(size_t)rr * 64 + col]     = v0 * f;
                    g_y[(size_t)rr * 64 + col + 1] = v1 * f;
                } else {
                    zsem[(size_t)rr * 32 + (col - 64)]     = v0 + bps[col - 64];
                    zsem[(size_t)rr * 32 + (col - 64) + 1] = v1 + bps[col - 63];
                }
            }
        }
    }
}

// ---------------- gather-aggregate + full tail fusion (1 warp / node) ----------------
__global__ __launch_bounds__(256) void k_agg(
    const float* __restrict__ bg,
    const float* __restrict__ Wpt, const float* __restrict__ bpt,
    const float* __restrict__ Wcls, const float* __restrict__ bcls,
    const float* __restrict__ zsem,
    float* __restrict__ logits, float* __restrict__ anom, float* __restrict__ ztopo)
{
    __shared__ float sWpt[64 * 32];
    __shared__ float sWcls[32 * 7];
    __shared__ float sbpt[32];
    __shared__ float sbcls[8];
    __shared__ float sbg[64];
    __shared__ float sh[8][64];
    __shared__ float sz[8][32];

    int tid = threadIdx.x;
    for (int i = tid; i < 64 * 32; i += 256) sWpt[i] = Wpt[i];
    for (int i = tid; i < 32 * 7;  i += 256) sWcls[i] = Wcls[i];
    if (tid < 32) sbpt[tid] = bpt[tid];
    if (tid < 7)  sbcls[tid] = bcls[tid];
    if (tid < 64) sbg[tid] = bg[tid];
    __syncthreads();

    int warp = tid >> 5, lane = tid & 31;
    int node = blockIdx.x * 8 + warp;
    if (node >= NN) return;

    const float2* y2 = (const float2*)g_y;
    float2 acc = y2[(size_t)node * 32 + lane];
    int p = g_rowptr[node], end = g_rowptr[node + 1];
    for (; p + 8 <= end; p += 8) {
        int s0 = g_csr[p],     s1 = g_csr[p + 1], s2 = g_csr[p + 2], s3 = g_csr[p + 3];
        int s4 = g_csr[p + 4], s5 = g_csr[p + 5], s6 = g_csr[p + 6], s7 = g_csr[p + 7];
        float2 v0 = y2[(size_t)s0 * 32 + lane];
        float2 v1 = y2[(size_t)s1 * 32 + lane];
        float2 v2 = y2[(size_t)s2 * 32 + lane];
        float2 v3 = y2[(size_t)s3 * 32 + lane];
        float2 v4 = y2[(size_t)s4 * 32 + lane];
        float2 v5 = y2[(size_t)s5 * 32 + lane];
        float2 v6 = y2[(size_t)s6 * 32 + lane];
        float2 v7 = y2[(size_t)s7 * 32 + lane];
        acc.x += ((v0.x + v1.x) + (v2.x + v3.x)) + ((v4.x + v5.x) + (v6.x + v7.x));
        acc.y += ((v0.y + v1.y) + (v2.y + v3.y)) + ((v4.y + v5.y) + (v6.y + v7.y));
    }
    for (; p < end; p++) {
        int s = g_csr[p];
        float2 v = y2[(size_t)s * 32 + lane];
        acc.x += v.x; acc.y += v.y;
    }

    float dn = g_dis[node];
    float h0 = fmaxf(fmaf(dn, acc.x, sbg[2 * lane]), 0.f);
    float h1 = fmaxf(fmaf(dn, acc.y, sbg[2 * lane + 1]), 0.f);
    sh[warp][2 * lane]     = h0;
    sh[warp][2 * lane + 1] = h1;
    __syncwarp();

    float z = sbpt[lane];
#pragma unroll
    for (int k = 0; k < 64; k++)
        z = fmaf(sh[warp][k], sWpt[k * 32 + lane], z);
    ztopo[(size_t)node * 32 + lane] = z;
    sz[warp][lane] = z;

    float d = z - zsem[(size_t)node * 32 + lane];
    float ss = d * d;
#pragma unroll
    for (int off = 16; off; off >>= 1) ss += __shfl_xor_sync(0xffffffffu, ss, off);
    if (lane == 0) anom[node] = sqrtf(ss);
    __syncwarp();

    if (lane < NC) {
        float lg = sbcls[lane];
#pragma unroll
        for (int l = 0; l < 32; l++)
            lg = fmaf(sz[warp][l], sWcls[l * 7 + lane], lg);
        logits[(size_t)node * 7 + lane] = lg;
    }
}

// ---------------- launch ----------------
extern "C" void kernel_launch(void* const* d_in, const int* in_sizes, int n_in,
                              void* d_out, int out_size)
{
    const float* x    = (const float*)d_in[0];
    const int*   ei   = (const int*)  d_in[1];
    const float* Wg   = (const float*)d_in[2];
    const float* bg   = (const float*)d_in[3];
    const float* Wpt  = (const float*)d_in[4];
    const float* bpt  = (const float*)d_in[5];
    const float* Wps  = (const float*)d_in[6];
    const float* bps  = (const float*)d_in[7];
    const float* Wcls = (const float*)d_in[8];
    const float* bcls = (const float*)d_in[9];

    float* out    = (float*)d_out;               // [logits | anomaly | z_topo | z_sem]
    float* logits = out;
    float* anom   = out + (size_t)NN * NC;
    float* ztopo  = anom + NN;
    float* zsem   = ztopo + (size_t)NN * 32;

    cudaFuncSetAttribute(k_gemm, cudaFuncAttributeMaxDynamicSharedMemorySize, SMEM_GEMM);

    k_zero_deg<<<(NN + 255) / 256, 256>>>();
    k_count  <<<(EE / 4 + 255) / 256, 256>>>(ei);
    k_scanA  <<<196, 256>>>();
    k_scanB  <<<1, 256>>>();
    k_scanC  <<<196, 256>>>();
    k_scatter<<<(EE + 255) / 256, 256>>>(ei);
    k_convB  <<<(96 * KP2 + 255) / 256, 256>>>(Wg, Wps);
    k_gemm   <<<(NN + 127) / 128, 256, SMEM_GEMM>>>(x, bps, zsem);
    k_agg    <<<(NN + 7) / 8, 256>>>(bg, Wpt, bpt, Wcls, bcls, zsem, logits, anom, ztopo);
}